// round 6
// baseline (speedup 1.0000x reference)
#include <cuda_runtime.h>
#include <math.h>

// Problem constants
#define BB        4
#define NPTS      4096
#define MPTS      4096
#define TPB       1024
#define SRCB      128               // sources per block
#define PARTS     8                 // threads per source
#define BLK_PER_B 32                // blocks per batch
#define NBLK      (BB * BLK_PER_B)  // 128 blocks total, <=1 per SM
#define NPAIRS    (MPTS / 2)        // 2048 target pairs per batch
#define PPT       (NPAIRS / PARTS)  // 256 pairs per thread
#define PPS       (PPT / 2)         // 128 pairs per stream
#define ICP_STEPS 16
#define ICP_TOL   1e-6

// ---------------------------------------------------------------------------
// Device-global state. Counters are monotonic within a launch and reset by
// the final block -> replay-clean for CUDA graphs.
// ---------------------------------------------------------------------------
__device__ float    g_wsum[BB][128][16];   // [b][warprow = oldblk*8 + w][q]
__device__ float    g_Rt[BB][12];
__device__ double   g_errlast[BB];
__device__ int      g_done;
__device__ unsigned g_gen;
__device__ unsigned g_momcnt;

// ---------------------------------------------------------------------------
__device__ __forceinline__ void xform(const float* Mtx,
                                      float px, float py, float pz,
                                      float& qx, float& qy, float& qz) {
    qx = fmaf(Mtx[0], px, fmaf(Mtx[1], py, fmaf(Mtx[2], pz, Mtx[9])));
    qy = fmaf(Mtx[3], px, fmaf(Mtx[4], py, fmaf(Mtx[5], pz, Mtx[10])));
    qz = fmaf(Mtx[6], px, fmaf(Mtx[7], py, fmaf(Mtx[8], pz, Mtx[11])));
}

__device__ __forceinline__ unsigned int fmono(float f) {
    unsigned int b = __float_as_uint(f);
    return (b & 0x80000000u) ? ~b : (b | 0x80000000u);
}
__device__ __forceinline__ float fmono_inv(unsigned int m) {
    unsigned int b = (m & 0x80000000u) ? (m ^ 0x80000000u) : ~m;
    return __uint_as_float(b);
}

// packed f32x2 helpers (per-half rounding identical to scalar FFMA)
__device__ __forceinline__ unsigned long long pk2(float v) {
    unsigned long long r;
    asm("mov.b64 %0, {%1, %1};" : "=l"(r) : "f"(v));
    return r;
}
__device__ __forceinline__ unsigned long long fma2(unsigned long long a,
                                                   unsigned long long b,
                                                   unsigned long long c) {
    unsigned long long d;
    asm("fma.rn.f32x2 %0, %1, %2, %3;" : "=l"(d) : "l"(a), "l"(b), "l"(c));
    return d;
}
__device__ __forceinline__ void upk2(unsigned long long v, float& lo, float& hi) {
    asm("mov.b64 {%0, %1}, %2;" : "=f"(lo), "=f"(hi) : "l"(v));
}

// ---------------------------------------------------------------------------
// Kabsch from accumulated sums (identical arithmetic to R2-R5).
// ---------------------------------------------------------------------------
__device__ void kabsch_sums(const double* S, float* Rt) {
    const double invN = 1.0 / (double)NPTS;
    double cs[3] = { S[0] * invN, S[1] * invN, S[2] * invN };
    double ct[3] = { S[3] * invN, S[4] * invN, S[5] * invN };

    float H[3][3];
    for (int i = 0; i < 3; ++i)
        for (int j = 0; j < 3; ++j)
            H[i][j] = (float)(S[6 + 3 * i + j] - (double)NPTS * cs[i] * ct[j]);

    float A[3][3];
    for (int i = 0; i < 3; ++i)
        for (int j = 0; j < 3; ++j)
            A[i][j] = H[0][i] * H[0][j] + H[1][i] * H[1][j] + H[2][i] * H[2][j];

    float V[3][3] = { {1,0,0},{0,1,0},{0,0,1} };
    const float diagmag = fabsf(A[0][0]) + fabsf(A[1][1]) + fabsf(A[2][2]);
    const float offeps  = diagmag * 1e-9f;
    for (int sweep = 0; sweep < 8; ++sweep) {
        const float off = fabsf(A[0][1]) + fabsf(A[0][2]) + fabsf(A[1][2]);
        if (off <= offeps) break;
        for (int pq = 0; pq < 3; ++pq) {
            const int p = (pq == 2) ? 1 : 0;
            const int q = (pq == 0) ? 1 : 2;
            const float apq = A[p][q];
            if (fabsf(apq) <= 0.0f) continue;
            const float theta = (A[q][q] - A[p][p]) / (2.0f * apq);
            const float tt = ((theta >= 0.0f) ? 1.0f : -1.0f) /
                             (fabsf(theta) + sqrtf(theta * theta + 1.0f));
            const float c = rsqrtf(tt * tt + 1.0f);
            const float s = tt * c;
            for (int k = 0; k < 3; ++k) { float a1 = A[p][k], a2 = A[q][k];
                A[p][k] = c * a1 - s * a2; A[q][k] = s * a1 + c * a2; }
            for (int k = 0; k < 3; ++k) { float a1 = A[k][p], a2 = A[k][q];
                A[k][p] = c * a1 - s * a2; A[k][q] = s * a1 + c * a2; }
            for (int k = 0; k < 3; ++k) { float v1 = V[k][p], v2 = V[k][q];
                V[k][p] = c * v1 - s * v2; V[k][q] = s * v1 + c * v2; }
        }
    }

    int id[3] = { 0, 1, 2 };
    float w[3] = { A[0][0], A[1][1], A[2][2] };
    if (w[id[0]] < w[id[1]]) { int t0 = id[0]; id[0] = id[1]; id[1] = t0; }
    if (w[id[0]] < w[id[2]]) { int t0 = id[0]; id[0] = id[2]; id[2] = t0; }
    if (w[id[1]] < w[id[2]]) { int t0 = id[1]; id[1] = id[2]; id[2] = t0; }

    float v1[3], v2[3], v3[3];
    for (int k = 0; k < 3; ++k) { v1[k] = V[k][id[0]]; v2[k] = V[k][id[1]]; v3[k] = V[k][id[2]]; }

    float u1[3], u2[3], u3[3];
    for (int i = 0; i < 3; ++i) u1[i] = H[i][0] * v1[0] + H[i][1] * v1[1] + H[i][2] * v1[2];
    {
        float n1 = u1[0]*u1[0] + u1[1]*u1[1] + u1[2]*u1[2];
        float r = (n1 > 0.0f) ? rsqrtf(n1) : 0.0f;
        u1[0] *= r; u1[1] *= r; u1[2] *= r;
    }
    for (int i = 0; i < 3; ++i) u2[i] = H[i][0] * v2[0] + H[i][1] * v2[1] + H[i][2] * v2[2];
    {
        float pr = u1[0]*u2[0] + u1[1]*u2[1] + u1[2]*u2[2];
        u2[0] -= pr * u1[0]; u2[1] -= pr * u1[1]; u2[2] -= pr * u1[2];
        float n2 = u2[0]*u2[0] + u2[1]*u2[1] + u2[2]*u2[2];
        float r = (n2 > 0.0f) ? rsqrtf(n2) : 0.0f;
        u2[0] *= r; u2[1] *= r; u2[2] *= r;
    }
    u3[0] = u1[1]*u2[2] - u1[2]*u2[1];
    u3[1] = u1[2]*u2[0] - u1[0]*u2[2];
    u3[2] = u1[0]*u2[1] - u1[1]*u2[0];

    const float d =
        v1[0] * (v2[1]*v3[2] - v2[2]*v3[1]) -
        v1[1] * (v2[0]*v3[2] - v2[2]*v3[0]) +
        v1[2] * (v2[0]*v3[1] - v2[1]*v3[0]);

    float R[9];
    for (int i = 0; i < 3; ++i)
        for (int j = 0; j < 3; ++j)
            R[3 * i + j] = v1[i]*u1[j] + v2[i]*u2[j] + d * v3[i]*u3[j];
    for (int k = 0; k < 9; ++k) Rt[k] = R[k];
    for (int i = 0; i < 3; ++i)
        Rt[9 + i] = (float)ct[i] - (R[3*i]*(float)cs[0] + R[3*i+1]*(float)cs[1]
                                    + R[3*i+2]*(float)cs[2]);
}

// ---------------------------------------------------------------------------
// Moment reduction for one source value set: warp shfl tree identical to the
// old block_reduce16 intra-warp stage; lane0 writes its warp row to g_wsum.
// Caller: threads 0..127 only (4 full warps).
// ---------------------------------------------------------------------------
__device__ __forceinline__ void warp_reduce16_store(const float v[16],
                                                    int b, int row) {
    const int lane = threadIdx.x & 31;
#pragma unroll
    for (int q = 0; q < 16; ++q) {
        float r = v[q];
#pragma unroll
        for (int o = 16; o > 0; o >>= 1) r += __shfl_down_sync(0xffffffffu, r, o);
        if (lane == 0) g_wsum[b][row][q] = r;
    }
}

// ---------------------------------------------------------------------------
// Persistent fused ICP kernel: 128 blocks x 1024 threads (<=1 block/SM).
// Block owns 128 sources; all 4096 targets of its batch staged in smem.
// 8 threads per source scan interleaved pair-strides; per-source argmin via
// 8-lane shfl min of packed keys (exact first-wins argmin).
// ---------------------------------------------------------------------------
extern __shared__ __align__(16) float smem_dyn[];

__global__ void __launch_bounds__(TPB, 1)
icp_kernel(const float* __restrict__ src, const float* __restrict__ tgt,
           float* __restrict__ out) {
    // dynamic smem layout
    float*              tgP  = smem_dyn;                         // 2048 pairs * 8 f = 64KB
    float*              srcP = tgP + NPAIRS * 8;                 // 128*3
    float*              mw   = srcP + SRCB * 3;                  // 128*3
    unsigned long long* mkey = (unsigned long long*)(mw + SRCB * 3);  // 128 (16B-aligned)
    float*              RtSh = (float*)(mkey + SRCB);            // 12

    __shared__ double sums[BB][16];
    __shared__ float  Rsh[BB][12];
    __shared__ int    convf[BB];
    __shared__ int    s_isfin;
    __shared__ int    s_done;

    const int tid  = threadIdx.x;
    const int b    = blockIdx.x >> 5;          // batch
    const int blk2 = blockIdx.x & 31;          // 128-source slice
    const int srcl = tid >> 3;                 // 0..127 local source
    const int part = tid & 7;                  // 0..7 target partition
    const int nloc = blk2 * SRCB + srcl;       // source index within batch
    const int gsrc = b * NPTS + nloc;          // global source index

    // ---- stage full target set of this batch; pair p: [x0 x1 y0 y1 z0 z1 w0 w1]
    {
        const float* T = tgt + (size_t)b * MPTS * 3;
        for (int k = tid; k < MPTS; k += TPB) {
            float x = T[3 * k], y = T[3 * k + 1], z = T[3 * k + 2];
            float w = fmaf(x, x, fmaf(y, y, z * z));
            int p = k >> 1, h = k & 1;
            tgP[p * 8 + 0 + h] = x;
            tgP[p * 8 + 2 + h] = y;
            tgP[p * 8 + 4 + h] = z;
            tgP[p * 8 + 6 + h] = w;
        }
    }
    // ---- stage this block's 128 source points
    if (tid < SRCB * 3) {
        srcP[tid] = src[(size_t)(b * NPTS + blk2 * SRCB) * 3 + tid];
    }
    __syncthreads();

    const ulonglong2* tg2 = (const ulonglong2*)tgP;   // pair p = tg2[2p], tg2[2p+1]

    for (int k = 0; k < ICP_STEPS; ++k) {
        // ---- wait for generation k, stage transform
        if (k > 0) {
            if (tid == 0) {
                while (*(volatile unsigned*)&g_gen < (unsigned)k) __nanosleep(32);
                __threadfence();
            }
            __syncthreads();
            if (tid < 12) RtSh[tid] = g_Rt[b][tid];
            __syncthreads();
        }

        // ---- transform own source point (identity at k==0, same bits as old)
        const float px = srcP[3 * srcl], py = srcP[3 * srcl + 1], pz = srcP[3 * srcl + 2];
        float wx, wy, wz;
        if (k == 0) {
            const float I[12] = {1.f,0.f,0.f, 0.f,1.f,0.f, 0.f,0.f,1.f, 0.f,0.f,0.f};
            xform(I, px, py, pz, wx, wy, wz);
        } else {
            xform(RtSh, px, py, pz, wx, wy, wz);
        }

        // ---- NN scan: this thread handles pairs p = part + 8*i, two streams
        const unsigned long long ax2 = pk2(-2.f * wx);
        const unsigned long long ay2 = pk2(-2.f * wy);
        const unsigned long long az2 = pk2(-2.f * wz);

        float smin0 = 3.4e38f, smin1 = 3.4e38f;
        int   jb0 = 0, jb1 = 0;

#pragma unroll 2
        for (int i = 0; i < PPS; ++i) {
            const int p0 = part + 8 * i;               // stream 0
            const int p1 = part + 8 * (i + PPS);       // stream 1
            const ulonglong2 A0 = tg2[2 * p0];
            const ulonglong2 B0 = tg2[2 * p0 + 1];
            const ulonglong2 A1 = tg2[2 * p1];
            const ulonglong2 B1 = tg2[2 * p1 + 1];

            unsigned long long s0 = fma2(ax2, A0.x, fma2(ay2, A0.y, fma2(az2, B0.x, B0.y)));
            unsigned long long s1 = fma2(ax2, A1.x, fma2(ay2, A1.y, fma2(az2, B1.x, B1.y)));

            float e0, o0, e1, o1;
            upk2(s0, e0, o0); upk2(s1, e1, o1);

            if (e0 < smin0) { smin0 = e0; jb0 = 2 * p0; }
            if (o0 < smin0) { smin0 = o0; jb0 = 2 * p0 + 1; }
            if (e1 < smin1) { smin1 = e1; jb1 = 2 * p1; }
            if (o1 < smin1) { smin1 = o1; jb1 = 2 * p1 + 1; }
        }

        // packed-key min == exact global first-wins argmin (ties -> smaller j)
        unsigned long long key0 = ((unsigned long long)fmono(smin0) << 16) | (unsigned)jb0;
        unsigned long long key1 = ((unsigned long long)fmono(smin1) << 16) | (unsigned)jb1;
        unsigned long long key  = min(key0, key1);

        // ---- 8-lane shfl min merge across parts of this source
#pragma unroll
        for (int o = 4; o > 0; o >>= 1)
            key = min(key, __shfl_down_sync(0xffffffffu, key, o, 8));

        if (part == 0) {
            mkey[srcl] = key;
            mw[3 * srcl] = wx; mw[3 * srcl + 1] = wy; mw[3 * srcl + 2] = wz;
        }
        __syncthreads();

        // ---- moments: threads 0..127, source = tid (same warp/lane order as
        //      the old 256-thread layout -> bit-identical reduction tree)
        if (tid < SRCB) {
            const unsigned long long kk = mkey[tid];
            const unsigned j = (unsigned)(kk & 0xFFFFu);
            const float    s = fmono_inv((unsigned int)(kk >> 16));
            const float mx = mw[3 * tid], my = mw[3 * tid + 1], mz = mw[3 * tid + 2];

            const float a2v = fmaf(mx, mx, fmaf(my, my, mz * mz));
            const float d2  = fmaxf(s + a2v, 0.f);
            const float ec  = sqrtf(d2);

            const unsigned p = j >> 1, h = j & 1;
            const float tx = tgP[p * 8 + 0 + h];
            const float ty = tgP[p * 8 + 2 + h];
            const float tz = tgP[p * 8 + 4 + h];

            const float v[16] = { mx, my, mz, tx, ty, tz,
                                  mx * tx, mx * ty, mx * tz,
                                  my * tx, my * ty, my * tz,
                                  mz * tx, mz * ty, mz * tz, ec };
            warp_reduce16_store(v, b, blk2 * 4 + (tid >> 5));

            // update the cloud (owned by this block)
            srcP[3 * tid] = mx; srcP[3 * tid + 1] = my; srcP[3 * tid + 2] = mz;
        }
        __threadfence();
        __syncthreads();

        if (tid == 0) {
            unsigned old = atomicAdd(&g_momcnt, 1u);
            s_isfin = (old == (unsigned)(NBLK * (k + 1) - 1)) ? 1 : 0;
        }
        __syncthreads();

        if (s_isfin) {
            // ---- FIN: last arriving block finalizes the step for all batches
            if (tid == 0) __threadfence();
            __syncthreads();
            if (tid < BB * 16) {
                const int bb = tid >> 4, q = tid & 15;
                double acc64 = 0.0;
                for (int bx = 0; bx < 16; ++bx) {      // old blk order
                    float acc32 = 0.f;
#pragma unroll
                    for (int w = 0; w < 8; ++w)        // old warp order
                        acc32 += g_wsum[bb][bx * 8 + w][q];
                    acc64 += (double)acc32;
                }
                sums[bb][q] = acc64;
            }
            __syncthreads();

            double errnew = 0.0;
            if (tid < BB) {
                errnew = sums[tid][15] / (double)NPTS;
                const double errlast = (k == 0) ? 0.0 : g_errlast[tid];
                convf[tid] = (fabs(errnew - errlast) < ICP_TOL) ? 1 : 0;
                kabsch_sums(sums[tid], Rsh[tid]);
            }
            __syncthreads();
            if (tid == 0) {
                const int all  = convf[0] & convf[1] & convf[2] & convf[3];
                const int prev = (k == 0) ? 0 : g_done;
                s_done = prev | all;
                g_done = s_done;
            }
            __syncthreads();
            if (tid < BB) {
                if (!s_done) {
                    g_errlast[tid] = errnew;
                    for (int q = 0; q < 12; ++q) g_Rt[tid][q] = Rsh[tid][q];
                } else {
                    for (int q = 0; q < 12; ++q)
                        g_Rt[tid][q] = (q == 0 || q == 4 || q == 8) ? 1.f : 0.f;
                }
            }
            __threadfence();
            __syncthreads();
            if (tid == 0) atomicExch(&g_gen, (unsigned)(k + 1));   // release
        }
    }

    // ======================= FINAL kabsch(source, temporal) ==================
    if (tid == 0) {
        while (*(volatile unsigned*)&g_gen < (unsigned)ICP_STEPS) __nanosleep(32);
        __threadfence();
    }
    __syncthreads();
    if (tid < 12) RtSh[tid] = g_Rt[b][tid];
    __syncthreads();

    if (tid < SRCB) {
        const float px = srcP[3 * tid], py = srcP[3 * tid + 1], pz = srcP[3 * tid + 2];
        float wx, wy, wz;
        xform(RtSh, px, py, pz, wx, wy, wz);

        const float sx = src[3 * (b * NPTS + blk2 * SRCB + tid)];
        const float sy = src[3 * (b * NPTS + blk2 * SRCB + tid) + 1];
        const float sz = src[3 * (b * NPTS + blk2 * SRCB + tid) + 2];

        const float v[16] = { sx, sy, sz, wx, wy, wz,
                              sx * wx, sx * wy, sx * wz,
                              sy * wx, sy * wy, sy * wz,
                              sz * wx, sz * wy, sz * wz, 0.f };
        warp_reduce16_store(v, b, blk2 * 4 + (tid >> 5));
    }
    __threadfence();
    __syncthreads();
    if (tid == 0) {
        unsigned old = atomicAdd(&g_momcnt, 1u);
        s_isfin = (old == (unsigned)(NBLK * (ICP_STEPS + 1) - 1)) ? 1 : 0;
    }
    __syncthreads();
    if (!s_isfin) return;

    // ---- last block: final kabsch, output, counter reset for next replay
    if (tid == 0) __threadfence();
    __syncthreads();
    if (tid < BB * 16) {
        const int bb = tid >> 4, q = tid & 15;
        double acc64 = 0.0;
        for (int bx = 0; bx < 16; ++bx) {
            float acc32 = 0.f;
#pragma unroll
            for (int w = 0; w < 8; ++w)
                acc32 += g_wsum[bb][bx * 8 + w][q];
            acc64 += (double)acc32;
        }
        sums[bb][q] = acc64;
    }
    __syncthreads();
    if (tid < BB) kabsch_sums(sums[tid], Rsh[tid]);
    __syncthreads();

    if (tid < BB * 12) {
        const int bb = tid / 12, q = tid % 12;
        const int i = q / 4, jj = q % 4;
        float val = (jj < 3) ? Rsh[bb][3 * i + jj] : Rsh[bb][9 + i];
        out[bb * 12 + i * 4 + jj] = val;
    }

    if (tid == 0) { g_gen = 0u; g_momcnt = 0u; }
}

// ---------------------------------------------------------------------------
extern "C" void kernel_launch(void* const* d_in, const int* in_sizes, int n_in,
                              void* d_out, int out_size) {
    const float* source = (const float*)d_in[0];
    const float* target = (const float*)d_in[1];
    float*       out    = (float*)d_out;

    const int smem_bytes = (NPAIRS * 8 + SRCB * 3 + SRCB * 3 + 12) * 4
                         + SRCB * 8 + 64;   // tgP + srcP + mw + RtSh + mkey + pad

    cudaFuncSetAttribute(icp_kernel,
                         cudaFuncAttributeMaxDynamicSharedMemorySize, smem_bytes);

    icp_kernel<<<NBLK, TPB, smem_bytes>>>(source, target, out);
}

// round 7
// speedup vs baseline: 2.4116x; 2.4116x over previous
#include <cuda_runtime.h>
#include <math.h>

// Problem constants
#define BB        4
#define NPTS      4096
#define MPTS      4096
#define TPB       1024
#define SRCB      128               // sources per block
#define PARTS     8                 // warps (target parts) per source group
#define BLK_PER_B 32                // blocks per batch
#define NBLK      (BB * BLK_PER_B)  // 128 blocks total, <=1 per SM
#define NPAIRS    (MPTS / 2)        // 2048 target pairs per batch
#define PPP       (NPAIRS / PARTS)  // 256 pairs per part
#define PPS       (PPP / 2)         // 128 pairs per stream
#define ICP_STEPS 16
#define ICP_TOL   1e-6

// ---------------------------------------------------------------------------
// Device-global state. Counters are monotonic within a launch and reset by
// the final block -> replay-clean for CUDA graphs.
// ---------------------------------------------------------------------------
__device__ float    g_wsum[BB][128][16];   // [b][warprow = oldblk*8 + w][q]
__device__ float    g_Rt[BB][12];
__device__ double   g_errlast[BB];
__device__ int      g_done;
__device__ unsigned g_gen;
__device__ unsigned g_momcnt;

// ---------------------------------------------------------------------------
__device__ __forceinline__ void xform(const float* Mtx,
                                      float px, float py, float pz,
                                      float& qx, float& qy, float& qz) {
    qx = fmaf(Mtx[0], px, fmaf(Mtx[1], py, fmaf(Mtx[2], pz, Mtx[9])));
    qy = fmaf(Mtx[3], px, fmaf(Mtx[4], py, fmaf(Mtx[5], pz, Mtx[10])));
    qz = fmaf(Mtx[6], px, fmaf(Mtx[7], py, fmaf(Mtx[8], pz, Mtx[11])));
}

__device__ __forceinline__ unsigned int fmono(float f) {
    unsigned int b = __float_as_uint(f);
    return (b & 0x80000000u) ? ~b : (b | 0x80000000u);
}
__device__ __forceinline__ float fmono_inv(unsigned int m) {
    unsigned int b = (m & 0x80000000u) ? (m ^ 0x80000000u) : ~m;
    return __uint_as_float(b);
}

// packed f32x2 helpers (per-half rounding identical to scalar FFMA)
__device__ __forceinline__ unsigned long long pk2(float v) {
    unsigned long long r;
    asm("mov.b64 %0, {%1, %1};" : "=l"(r) : "f"(v));
    return r;
}
__device__ __forceinline__ unsigned long long fma2(unsigned long long a,
                                                   unsigned long long b,
                                                   unsigned long long c) {
    unsigned long long d;
    asm("fma.rn.f32x2 %0, %1, %2, %3;" : "=l"(d) : "l"(a), "l"(b), "l"(c));
    return d;
}
__device__ __forceinline__ void upk2(unsigned long long v, float& lo, float& hi) {
    asm("mov.b64 {%0, %1}, %2;" : "=f"(lo), "=f"(hi) : "l"(v));
}

// ---------------------------------------------------------------------------
// Kabsch from accumulated sums (identical arithmetic to R2-R6).
// ---------------------------------------------------------------------------
__device__ void kabsch_sums(const double* S, float* Rt) {
    const double invN = 1.0 / (double)NPTS;
    double cs[3] = { S[0] * invN, S[1] * invN, S[2] * invN };
    double ct[3] = { S[3] * invN, S[4] * invN, S[5] * invN };

    float H[3][3];
    for (int i = 0; i < 3; ++i)
        for (int j = 0; j < 3; ++j)
            H[i][j] = (float)(S[6 + 3 * i + j] - (double)NPTS * cs[i] * ct[j]);

    float A[3][3];
    for (int i = 0; i < 3; ++i)
        for (int j = 0; j < 3; ++j)
            A[i][j] = H[0][i] * H[0][j] + H[1][i] * H[1][j] + H[2][i] * H[2][j];

    float V[3][3] = { {1,0,0},{0,1,0},{0,0,1} };
    const float diagmag = fabsf(A[0][0]) + fabsf(A[1][1]) + fabsf(A[2][2]);
    const float offeps  = diagmag * 1e-9f;
    for (int sweep = 0; sweep < 8; ++sweep) {
        const float off = fabsf(A[0][1]) + fabsf(A[0][2]) + fabsf(A[1][2]);
        if (off <= offeps) break;
        for (int pq = 0; pq < 3; ++pq) {
            const int p = (pq == 2) ? 1 : 0;
            const int q = (pq == 0) ? 1 : 2;
            const float apq = A[p][q];
            if (fabsf(apq) <= 0.0f) continue;
            const float theta = (A[q][q] - A[p][p]) / (2.0f * apq);
            const float tt = ((theta >= 0.0f) ? 1.0f : -1.0f) /
                             (fabsf(theta) + sqrtf(theta * theta + 1.0f));
            const float c = rsqrtf(tt * tt + 1.0f);
            const float s = tt * c;
            for (int k = 0; k < 3; ++k) { float a1 = A[p][k], a2 = A[q][k];
                A[p][k] = c * a1 - s * a2; A[q][k] = s * a1 + c * a2; }
            for (int k = 0; k < 3; ++k) { float a1 = A[k][p], a2 = A[k][q];
                A[k][p] = c * a1 - s * a2; A[k][q] = s * a1 + c * a2; }
            for (int k = 0; k < 3; ++k) { float v1 = V[k][p], v2 = V[k][q];
                V[k][p] = c * v1 - s * v2; V[k][q] = s * v1 + c * v2; }
        }
    }

    int id[3] = { 0, 1, 2 };
    float w[3] = { A[0][0], A[1][1], A[2][2] };
    if (w[id[0]] < w[id[1]]) { int t0 = id[0]; id[0] = id[1]; id[1] = t0; }
    if (w[id[0]] < w[id[2]]) { int t0 = id[0]; id[0] = id[2]; id[2] = t0; }
    if (w[id[1]] < w[id[2]]) { int t0 = id[1]; id[1] = id[2]; id[2] = t0; }

    float v1[3], v2[3], v3[3];
    for (int k = 0; k < 3; ++k) { v1[k] = V[k][id[0]]; v2[k] = V[k][id[1]]; v3[k] = V[k][id[2]]; }

    float u1[3], u2[3], u3[3];
    for (int i = 0; i < 3; ++i) u1[i] = H[i][0] * v1[0] + H[i][1] * v1[1] + H[i][2] * v1[2];
    {
        float n1 = u1[0]*u1[0] + u1[1]*u1[1] + u1[2]*u1[2];
        float r = (n1 > 0.0f) ? rsqrtf(n1) : 0.0f;
        u1[0] *= r; u1[1] *= r; u1[2] *= r;
    }
    for (int i = 0; i < 3; ++i) u2[i] = H[i][0] * v2[0] + H[i][1] * v2[1] + H[i][2] * v2[2];
    {
        float pr = u1[0]*u2[0] + u1[1]*u2[1] + u1[2]*u2[2];
        u2[0] -= pr * u1[0]; u2[1] -= pr * u1[1]; u2[2] -= pr * u1[2];
        float n2 = u2[0]*u2[0] + u2[1]*u2[1] + u2[2]*u2[2];
        float r = (n2 > 0.0f) ? rsqrtf(n2) : 0.0f;
        u2[0] *= r; u2[1] *= r; u2[2] *= r;
    }
    u3[0] = u1[1]*u2[2] - u1[2]*u2[1];
    u3[1] = u1[2]*u2[0] - u1[0]*u2[2];
    u3[2] = u1[0]*u2[1] - u1[1]*u2[0];

    const float d =
        v1[0] * (v2[1]*v3[2] - v2[2]*v3[1]) -
        v1[1] * (v2[0]*v3[2] - v2[2]*v3[0]) +
        v1[2] * (v2[0]*v3[1] - v2[1]*v3[0]);

    float R[9];
    for (int i = 0; i < 3; ++i)
        for (int j = 0; j < 3; ++j)
            R[3 * i + j] = v1[i]*u1[j] + v2[i]*u2[j] + d * v3[i]*u3[j];
    for (int k = 0; k < 9; ++k) Rt[k] = R[k];
    for (int i = 0; i < 3; ++i)
        Rt[9 + i] = (float)ct[i] - (R[3*i]*(float)cs[0] + R[3*i+1]*(float)cs[1]
                                    + R[3*i+2]*(float)cs[2]);
}

// ---------------------------------------------------------------------------
// Warp shfl reduction identical to the old block_reduce16 intra-warp stage;
// lane0 writes its warp row to g_wsum. Caller: threads 0..127 only.
// ---------------------------------------------------------------------------
__device__ __forceinline__ void warp_reduce16_store(const float v[16],
                                                    int b, int row) {
    const int lane = threadIdx.x & 31;
#pragma unroll
    for (int q = 0; q < 16; ++q) {
        float r = v[q];
#pragma unroll
        for (int o = 16; o > 0; o >>= 1) r += __shfl_down_sync(0xffffffffu, r, o);
        if (lane == 0) g_wsum[b][row][q] = r;
    }
}

// ---------------------------------------------------------------------------
// Persistent fused ICP kernel: 128 blocks x 1024 threads (1 block/SM).
// Warp w: source-group g=w>>3 (32 sources, one per LANE -> broadcast loads),
// part q=w&7 scans contiguous pair range [q*256,(q+1)*256).
// Per-source argmin across the 8 parts merged via smem packed-key min (exact).
// ---------------------------------------------------------------------------
extern __shared__ __align__(16) float smem_dyn[];

__global__ void __launch_bounds__(TPB, 1)
icp_kernel(const float* __restrict__ src, const float* __restrict__ tgt,
           float* __restrict__ out) {
    // dynamic smem layout
    float*              tgP  = smem_dyn;                          // 2048 pairs * 8 f = 64KB
    float*              srcP = tgP + NPAIRS * 8;                  // 128*3
    float*              mw   = srcP + SRCB * 3;                   // 128*3
    unsigned long long* skey = (unsigned long long*)(mw + SRCB * 3 + 2); // 1024 (8B-aligned)
    float*              RtSh = (float*)(skey + TPB);              // 12

    __shared__ double sums[BB][16];
    __shared__ float  Rsh[BB][12];
    __shared__ int    convf[BB];
    __shared__ int    s_isfin;
    __shared__ int    s_done;

    const int tid  = threadIdx.x;
    const int w    = tid >> 5;                 // warp 0..31
    const int lane = tid & 31;
    const int g    = w >> 3;                   // source group 0..3
    const int q    = w & 7;                    // target part 0..7
    const int srcl = g * 32 + lane;            // this lane's source (scan phase)
    const int b    = blockIdx.x >> 5;          // batch
    const int blk2 = blockIdx.x & 31;          // 128-source slice

    // ---- stage full target set of this batch; pair p: [x0 x1 y0 y1 z0 z1 w0 w1]
    {
        const float* T = tgt + (size_t)b * MPTS * 3;
        for (int k = tid; k < MPTS; k += TPB) {
            float x = T[3 * k], y = T[3 * k + 1], z = T[3 * k + 2];
            float ww = fmaf(x, x, fmaf(y, y, z * z));
            int p = k >> 1, h = k & 1;
            tgP[p * 8 + 0 + h] = x;
            tgP[p * 8 + 2 + h] = y;
            tgP[p * 8 + 4 + h] = z;
            tgP[p * 8 + 6 + h] = ww;
        }
    }
    // ---- stage this block's 128 source points
    if (tid < SRCB * 3) {
        srcP[tid] = src[(size_t)(b * NPTS + blk2 * SRCB) * 3 + tid];
    }
    __syncthreads();

    const ulonglong2* tg2 = (const ulonglong2*)tgP;   // pair p = tg2[2p], tg2[2p+1]

    for (int k = 0; k < ICP_STEPS; ++k) {
        // ---- wait for generation k, stage transform
        if (k > 0) {
            if (tid == 0) {
                while (*(volatile unsigned*)&g_gen < (unsigned)k) __nanosleep(32);
                __threadfence();
            }
            __syncthreads();
            if (tid < 12) RtSh[tid] = g_Rt[b][tid];
            __syncthreads();
        }

        // ---- transform this lane's source point (identity at k==0)
        const float px = srcP[3 * srcl], py = srcP[3 * srcl + 1], pz = srcP[3 * srcl + 2];
        float wx, wy, wz;
        if (k == 0) {
            const float I[12] = {1.f,0.f,0.f, 0.f,1.f,0.f, 0.f,0.f,1.f, 0.f,0.f,0.f};
            xform(I, px, py, pz, wx, wy, wz);
        } else {
            xform(RtSh, px, py, pz, wx, wy, wz);
        }

        // ---- NN scan over contiguous part range, 2 contiguous streams.
        //      Warp-uniform addresses -> broadcast LDS (N=1, minimal L1 traffic).
        const unsigned long long ax2 = pk2(-2.f * wx);
        const unsigned long long ay2 = pk2(-2.f * wy);
        const unsigned long long az2 = pk2(-2.f * wz);

        const int pbase = q * PPP;             // first pair of this part

        float smin0 = 3.4e38f, smin1 = 3.4e38f;
        int   jb0 = 0, jb1 = 0;

#pragma unroll 4
        for (int i = 0; i < PPS; ++i) {
            const int p0 = pbase + i;           // stream 0: pairs [pbase, pbase+128)
            const int p1 = p0 + PPS;            // stream 1: pairs [pbase+128, pbase+256)
            const ulonglong2 A0 = tg2[2 * p0];
            const ulonglong2 B0 = tg2[2 * p0 + 1];
            const ulonglong2 A1 = tg2[2 * p1];
            const ulonglong2 B1 = tg2[2 * p1 + 1];

            unsigned long long s0 = fma2(ax2, A0.x, fma2(ay2, A0.y, fma2(az2, B0.x, B0.y)));
            unsigned long long s1 = fma2(ax2, A1.x, fma2(ay2, A1.y, fma2(az2, B1.x, B1.y)));

            float e0, o0, e1, o1;
            upk2(s0, e0, o0); upk2(s1, e1, o1);

            if (e0 < smin0) { smin0 = e0; jb0 = 2 * i; }
            if (o0 < smin0) { smin0 = o0; jb0 = 2 * i + 1; }
            if (e1 < smin1) { smin1 = e1; jb1 = 2 * i; }
            if (o1 < smin1) { smin1 = o1; jb1 = 2 * i + 1; }
        }

        // merge streams (ascending target order, strict <), build packed key
        float smin = smin0;
        int   jb   = jb0;
        if (smin1 < smin) { smin = smin1; jb = 2 * PPS + jb1; }
        const int jglob = 2 * pbase + jb;       // global target index of this part's best

        skey[w * 32 + lane] =
            ((unsigned long long)fmono(smin) << 16) | (unsigned)jglob;

        if (q == 0) {   // one copy of the transformed point per source
            mw[3 * srcl] = wx; mw[3 * srcl + 1] = wy; mw[3 * srcl + 2] = wz;
        }
        __syncthreads();

        // ---- moments: threads 0..127, source = tid (same warp/lane order as
        //      the original 256-thread layout -> bit-identical reduction tree)
        if (tid < SRCB) {
            const int g2 = tid >> 5, l2 = tid & 31;
            unsigned long long kk = skey[(g2 * 8 + 0) * 32 + l2];
#pragma unroll
            for (int qq = 1; qq < PARTS; ++qq)
                kk = min(kk, skey[(g2 * 8 + qq) * 32 + l2]);   // exact first-wins

            const unsigned j = (unsigned)(kk & 0xFFFFu);
            const float    s = fmono_inv((unsigned int)(kk >> 16));
            const float mx = mw[3 * tid], my = mw[3 * tid + 1], mz = mw[3 * tid + 2];

            const float a2v = fmaf(mx, mx, fmaf(my, my, mz * mz));
            const float d2  = fmaxf(s + a2v, 0.f);
            const float ec  = sqrtf(d2);

            const unsigned p = j >> 1, h = j & 1;
            const float tx = tgP[p * 8 + 0 + h];
            const float ty = tgP[p * 8 + 2 + h];
            const float tz = tgP[p * 8 + 4 + h];

            const float v[16] = { mx, my, mz, tx, ty, tz,
                                  mx * tx, mx * ty, mx * tz,
                                  my * tx, my * ty, my * tz,
                                  mz * tx, mz * ty, mz * tz, ec };
            warp_reduce16_store(v, b, blk2 * 4 + (tid >> 5));

            // update the cloud (owned by this block)
            srcP[3 * tid] = mx; srcP[3 * tid + 1] = my; srcP[3 * tid + 2] = mz;
        }
        __threadfence();
        __syncthreads();

        if (tid == 0) {
            unsigned old = atomicAdd(&g_momcnt, 1u);
            s_isfin = (old == (unsigned)(NBLK * (k + 1) - 1)) ? 1 : 0;
        }
        __syncthreads();

        if (s_isfin) {
            // ---- FIN: last arriving block finalizes the step for all batches
            if (tid == 0) __threadfence();
            __syncthreads();
            if (tid < BB * 16) {
                const int bb = tid >> 4, qq = tid & 15;
                double acc64 = 0.0;
                for (int bx = 0; bx < 16; ++bx) {
                    float acc32 = 0.f;
#pragma unroll
                    for (int ww = 0; ww < 8; ++ww)
                        acc32 += g_wsum[bb][bx * 8 + ww][qq];
                    acc64 += (double)acc32;
                }
                sums[bb][qq] = acc64;
            }
            __syncthreads();

            double errnew = 0.0;
            if (tid < BB) {
                errnew = sums[tid][15] / (double)NPTS;
                const double errlast = (k == 0) ? 0.0 : g_errlast[tid];
                convf[tid] = (fabs(errnew - errlast) < ICP_TOL) ? 1 : 0;
                kabsch_sums(sums[tid], Rsh[tid]);
            }
            __syncthreads();
            if (tid == 0) {
                const int all  = convf[0] & convf[1] & convf[2] & convf[3];
                const int prev = (k == 0) ? 0 : g_done;
                s_done = prev | all;
                g_done = s_done;
            }
            __syncthreads();
            if (tid < BB) {
                if (!s_done) {
                    g_errlast[tid] = errnew;
                    for (int qq = 0; qq < 12; ++qq) g_Rt[tid][qq] = Rsh[tid][qq];
                } else {
                    for (int qq = 0; qq < 12; ++qq)
                        g_Rt[tid][qq] = (qq == 0 || qq == 4 || qq == 8) ? 1.f : 0.f;
                }
            }
            __threadfence();
            __syncthreads();
            if (tid == 0) atomicExch(&g_gen, (unsigned)(k + 1));   // release
        }
    }

    // ======================= FINAL kabsch(source, temporal) ==================
    if (tid == 0) {
        while (*(volatile unsigned*)&g_gen < (unsigned)ICP_STEPS) __nanosleep(32);
        __threadfence();
    }
    __syncthreads();
    if (tid < 12) RtSh[tid] = g_Rt[b][tid];
    __syncthreads();

    if (tid < SRCB) {
        const float px = srcP[3 * tid], py = srcP[3 * tid + 1], pz = srcP[3 * tid + 2];
        float wx, wy, wz;
        xform(RtSh, px, py, pz, wx, wy, wz);

        const float sx = src[3 * (b * NPTS + blk2 * SRCB + tid)];
        const float sy = src[3 * (b * NPTS + blk2 * SRCB + tid) + 1];
        const float sz = src[3 * (b * NPTS + blk2 * SRCB + tid) + 2];

        const float v[16] = { sx, sy, sz, wx, wy, wz,
                              sx * wx, sx * wy, sx * wz,
                              sy * wx, sy * wy, sy * wz,
                              sz * wx, sz * wy, sz * wz, 0.f };
        warp_reduce16_store(v, b, blk2 * 4 + (tid >> 5));
    }
    __threadfence();
    __syncthreads();
    if (tid == 0) {
        unsigned old = atomicAdd(&g_momcnt, 1u);
        s_isfin = (old == (unsigned)(NBLK * (ICP_STEPS + 1) - 1)) ? 1 : 0;
    }
    __syncthreads();
    if (!s_isfin) return;

    // ---- last block: final kabsch, output, counter reset for next replay
    if (tid == 0) __threadfence();
    __syncthreads();
    if (tid < BB * 16) {
        const int bb = tid >> 4, qq = tid & 15;
        double acc64 = 0.0;
        for (int bx = 0; bx < 16; ++bx) {
            float acc32 = 0.f;
#pragma unroll
            for (int ww = 0; ww < 8; ++ww)
                acc32 += g_wsum[bb][bx * 8 + ww][qq];
            acc64 += (double)acc32;
        }
        sums[bb][qq] = acc64;
    }
    __syncthreads();
    if (tid < BB) kabsch_sums(sums[tid], Rsh[tid]);
    __syncthreads();

    if (tid < BB * 12) {
        const int bb = tid / 12, qq = tid % 12;
        const int i = qq / 4, jj = qq % 4;
        float val = (jj < 3) ? Rsh[bb][3 * i + jj] : Rsh[bb][9 + i];
        out[bb * 12 + i * 4 + jj] = val;
    }

    if (tid == 0) { g_gen = 0u; g_momcnt = 0u; }
}

// ---------------------------------------------------------------------------
extern "C" void kernel_launch(void* const* d_in, const int* in_sizes, int n_in,
                              void* d_out, int out_size) {
    const float* source = (const float*)d_in[0];
    const float* target = (const float*)d_in[1];
    float*       out    = (float*)d_out;

    const int smem_bytes = (NPAIRS * 8 + SRCB * 3 + SRCB * 3 + 2 + 12) * 4
                         + TPB * 8 + 64;   // tgP + srcP + mw + pad + RtSh + skey

    cudaFuncSetAttribute(icp_kernel,
                         cudaFuncAttributeMaxDynamicSharedMemorySize, smem_bytes);

    icp_kernel<<<NBLK, TPB, smem_bytes>>>(source, target, out);
}